// round 15
// baseline (speedup 1.0000x reference)
#include <cuda_runtime.h>

// PLIF spiking neuron forward — FINAL (R13, measured best: 35.84µs kernel,
// 5.92 TB/s = 74.7% DRAM busy).
//   x: [B=32, T=8, C=128, H=32, W=32] f32, tau: [C=128] f32
//   tau_s = sigmoid(tau[c])
//   scan over t: mem = mem*tau_s + x_t; spike = (mem - 1 > 0); mem = (1-spike)*mem
//
// 2 sites per thread (MLP=16), sites N4/2 apart so each warp stays fully
// coalesced in each half. All 16 LDG.128 front-batched, then both register
// scans with interleaved STG.128. 80 regs, 26-31% occ — occ x MLP saturates
// the SM load queue; DRAM% is invariant (73.9-74.7%) across 49%x8, 31%x16,
// 26%x16. Ruled out by experiment: .CS hints, store batching, grid-stride,
// persistent layouts, 256-thread blocks, bounds guard, hand-hoisted sigmoid.

constexpr int B = 32, T = 8, C = 128, H = 32, W = 32;
constexpr int HW   = H * W;          // 1024
constexpr int CHW  = C * HW;         // 131072 (= 2^17)
constexpr int TCHW = T * CHW;        // 1048576
constexpr int N4   = (B * CHW) / 4;  // 1048576 float4-sites
constexpr int HALF = N4 / 2;         // 524288

constexpr int THREADS = 128;
constexpr int BLOCKS  = HALF / THREADS;   // 4096 — exact cover

static_assert(BLOCKS * THREADS == HALF, "grid must cover HALF exactly");

__device__ __forceinline__ void plif_scan(const float4* __restrict__ v,
                                          float ts, int base, int tstride,
                                          float4* __restrict__ out4)
{
    float4 mem = make_float4(0.f, 0.f, 0.f, 0.f);
#pragma unroll
    for (int t = 0; t < T; t++) {
        float4 s;
        mem.x = mem.x * ts + v[t].x;
        mem.y = mem.y * ts + v[t].y;
        mem.z = mem.z * ts + v[t].z;
        mem.w = mem.w * ts + v[t].w;
        s.x = (mem.x > 1.0f) ? 1.0f : 0.0f;
        s.y = (mem.y > 1.0f) ? 1.0f : 0.0f;
        s.z = (mem.z > 1.0f) ? 1.0f : 0.0f;
        s.w = (mem.w > 1.0f) ? 1.0f : 0.0f;
        if (s.x != 0.0f) mem.x = 0.0f;
        if (s.y != 0.0f) mem.y = 0.0f;
        if (s.z != 0.0f) mem.z = 0.0f;
        if (s.w != 0.0f) mem.w = 0.0f;
        out4[base + t * tstride] = s;
    }
}

__global__ __launch_bounds__(THREADS) void plif_kernel(
    const float4* __restrict__ x4,
    const float*  __restrict__ tau,
    float4*       __restrict__ out4)
{
    constexpr int tstride = CHW >> 2;   // float4 stride between timesteps

    int idx0 = blockIdx.x * THREADS + threadIdx.x;  // [0, HALF)
    int idx1 = idx0 + HALF;                          // second site, same layout

    // Site 0 indexing
    int e0   = idx0 << 2;
    int b0   = e0 >> 17;
    int rem0 = e0 & (CHW - 1);
    int c0   = rem0 >> 10;
    int base0 = (b0 * TCHW + rem0) >> 2;

    // Site 1 indexing
    int e1   = idx1 << 2;
    int b1   = e1 >> 17;
    int rem1 = e1 & (CHW - 1);
    int c1   = rem1 >> 10;
    int base1 = (b1 * TCHW + rem1) >> 2;

    // Per-channel leaks (c0 == c1 by construction; ptxas CSEs the pair)
    float ts0 = 1.0f / (1.0f + expf(-tau[c0]));
    float ts1 = 1.0f / (1.0f + expf(-tau[c1]));

    // Front-batch all 16 independent LDG.128
    float4 v0[T], v1[T];
#pragma unroll
    for (int t = 0; t < T; t++)
        v0[t] = x4[base0 + t * tstride];
#pragma unroll
    for (int t = 0; t < T; t++)
        v1[t] = x4[base1 + t * tstride];

    // Scan + store both sites
    plif_scan(v0, ts0, base0, tstride, out4);
    plif_scan(v1, ts1, base1, tstride, out4);
}

extern "C" void kernel_launch(void* const* d_in, const int* in_sizes, int n_in,
                              void* d_out, int out_size)
{
    const float4* x4  = (const float4*)d_in[0];
    const float*  tau = (const float*)d_in[1];
    float4*       o4  = (float4*)d_out;

    plif_kernel<<<BLOCKS, THREADS>>>(x4, tau, o4);
}

// round 17
// speedup vs baseline: 1.0546x; 1.0546x over previous
#include <cuda_runtime.h>

// PLIF spiking neuron forward — FINAL (R13, measured best: 35.84µs kernel,
// 5.92 TB/s = 74.7% DRAM busy; re-confirmed R15 at 36.16µs / 74.1%).
//   x: [B=32, T=8, C=128, H=32, W=32] f32, tau: [C=128] f32
//   tau_s = sigmoid(tau[c])
//   scan over t: mem = mem*tau_s + x_t; spike = (mem - 1 > 0); mem = (1-spike)*mem
//
// 2 sites per thread (MLP=16), sites N4/2 apart so each warp stays fully
// coalesced in each half. All 16 LDG.128 front-batched, then both register
// scans with interleaved STG.128. 80 regs, ~30% occ — occ x MLP saturates
// the SM load queue; DRAM% is invariant (73.9-74.7%) across 49%x8, 31%x16,
// 26%x16. Ruled out by experiment over 9 variants: .CS hints, store
// batching, grid-stride, persistent layouts, 256-thread blocks, bounds
// guard, hand-hoisted sigmoid. This is the chip's mixed-R/W plateau.

constexpr int B = 32, T = 8, C = 128, H = 32, W = 32;
constexpr int HW   = H * W;          // 1024
constexpr int CHW  = C * HW;         // 131072 (= 2^17)
constexpr int TCHW = T * CHW;        // 1048576
constexpr int N4   = (B * CHW) / 4;  // 1048576 float4-sites
constexpr int HALF = N4 / 2;         // 524288

constexpr int THREADS = 128;
constexpr int BLOCKS  = HALF / THREADS;   // 4096 — exact cover

static_assert(BLOCKS * THREADS == HALF, "grid must cover HALF exactly");

__device__ __forceinline__ void plif_scan(const float4* __restrict__ v,
                                          float ts, int base, int tstride,
                                          float4* __restrict__ out4)
{
    float4 mem = make_float4(0.f, 0.f, 0.f, 0.f);
#pragma unroll
    for (int t = 0; t < T; t++) {
        float4 s;
        mem.x = mem.x * ts + v[t].x;
        mem.y = mem.y * ts + v[t].y;
        mem.z = mem.z * ts + v[t].z;
        mem.w = mem.w * ts + v[t].w;
        s.x = (mem.x > 1.0f) ? 1.0f : 0.0f;
        s.y = (mem.y > 1.0f) ? 1.0f : 0.0f;
        s.z = (mem.z > 1.0f) ? 1.0f : 0.0f;
        s.w = (mem.w > 1.0f) ? 1.0f : 0.0f;
        if (s.x != 0.0f) mem.x = 0.0f;
        if (s.y != 0.0f) mem.y = 0.0f;
        if (s.z != 0.0f) mem.z = 0.0f;
        if (s.w != 0.0f) mem.w = 0.0f;
        out4[base + t * tstride] = s;
    }
}

__global__ __launch_bounds__(THREADS) void plif_kernel(
    const float4* __restrict__ x4,
    const float*  __restrict__ tau,
    float4*       __restrict__ out4)
{
    constexpr int tstride = CHW >> 2;   // float4 stride between timesteps

    int idx0 = blockIdx.x * THREADS + threadIdx.x;  // [0, HALF)
    int idx1 = idx0 + HALF;                          // second site, same layout

    // Site 0 indexing
    int e0   = idx0 << 2;
    int b0   = e0 >> 17;
    int rem0 = e0 & (CHW - 1);
    int c0   = rem0 >> 10;
    int base0 = (b0 * TCHW + rem0) >> 2;

    // Site 1 indexing
    int e1   = idx1 << 2;
    int b1   = e1 >> 17;
    int rem1 = e1 & (CHW - 1);
    int c1   = rem1 >> 10;
    int base1 = (b1 * TCHW + rem1) >> 2;

    // Per-channel leaks (c0 == c1 by construction; ptxas CSEs the pair)
    float ts0 = 1.0f / (1.0f + expf(-tau[c0]));
    float ts1 = 1.0f / (1.0f + expf(-tau[c1]));

    // Front-batch all 16 independent LDG.128
    float4 v0[T], v1[T];
#pragma unroll
    for (int t = 0; t < T; t++)
        v0[t] = x4[base0 + t * tstride];
#pragma unroll
    for (int t = 0; t < T; t++)
        v1[t] = x4[base1 + t * tstride];

    // Scan + store both sites
    plif_scan(v0, ts0, base0, tstride, out4);
    plif_scan(v1, ts1, base1, tstride, out4);
}

extern "C" void kernel_launch(void* const* d_in, const int* in_sizes, int n_in,
                              void* d_out, int out_size)
{
    const float4* x4  = (const float4*)d_in[0];
    const float*  tau = (const float*)d_in[1];
    float4*       o4  = (float4*)d_out;

    plif_kernel<<<BLOCKS, THREADS>>>(x4, tau, o4);
}